// round 5
// baseline (speedup 1.0000x reference)
#include <cuda_runtime.h>

// ---------------------------------------------------------------------------
// DiscriminativeClueCorrection — fp32 FFMA2 GEMMs (pair-A/dup-B), restructured.
// Output layout (float32): [loss(1)] [corrected(512*512)] [cluster_scores(512*3)]
// ---------------------------------------------------------------------------

constexpr int kB    = 512;
constexpr int kM    = 96;
constexpr int kD    = 512;
constexpr int kH    = 8;
constexpr int kDH   = 64;
constexpr int kNC   = 3;
constexpr int kNegC = 1024;         // unique negative columns (cn ×512 + mem ×512)
constexpr float kEps = 1e-8f;

// ----- device scratch --------------------------------------------------------
__device__ float g_vn   [kB * kD];
__device__ float g_q    [kB * kD];
__device__ float g_qt   [kB * kH * kD];     // per-b transformed key weights (×1/8)
__device__ float g_tctx [kB * kH * kD];
__device__ float g_ctx  [kB * kD];
__device__ float g_corr [2 * kB * kD];      // split-K partials
__device__ float g_pos  [kB];
__device__ float g_negs [kNegC * kD];
__device__ float g_nsims[kB * kNegC];
__device__ float g_lossb[kB];

__device__ __forceinline__ float warp_sum(float v) {
#pragma unroll
    for (int o = 16; o > 0; o >>= 1) v += __shfl_xor_sync(0xffffffffu, v, o);
    return v;
}
__device__ __forceinline__ float warp_max(float v) {
#pragma unroll
    for (int o = 16; o > 0; o >>= 1) v = fmaxf(v, __shfl_xor_sync(0xffffffffu, v, o));
    return v;
}

// ----- f32x2 packed helpers ---------------------------------------------------
__device__ __forceinline__ unsigned long long dup2(float v) {
    unsigned long long r;
    asm("mov.b64 %0, {%1,%1};" : "=l"(r) : "f"(v));
    return r;
}
__device__ __forceinline__ void fma2(unsigned long long& acc, unsigned long long a,
                                     unsigned long long b) {
    asm("fma.rn.f32x2 %0, %1, %2, %0;" : "+l"(acc) : "l"(a), "l"(b));
}
__device__ __forceinline__ float2 unpack2(unsigned long long v) {
    float2 f;
    asm("mov.b64 {%0,%1}, %2;" : "=f"(f.x), "=f"(f.y) : "l"(v));
    return f;
}

// ----- merged: normalize vis rows (blocks 0..511) + memory negs (512..1023) ---
__global__ void k_pre(const float* __restrict__ vis, const float* __restrict__ tmem) {
    int t = threadIdx.x;                     // 256 threads
    __shared__ float red[8];
    if (blockIdx.x < kB) {
        int b = blockIdx.x;
        const float* x = vis + (size_t)b * kD;
        float ss = 0.f;
        for (int i = t; i < kD; i += 256) { float v = x[i]; ss += v * v; }
        ss = warp_sum(ss);
        if ((t & 31) == 0) red[t >> 5] = ss;
        __syncthreads();
        float tot = red[0] + red[1] + red[2] + red[3] + red[4] + red[5] + red[6] + red[7];
        float inv = 1.0f / fmaxf(sqrtf(tot), kEps);
        for (int i = t; i < kD; i += 256) g_vn[(size_t)b * kD + i] = x[i] * inv;
    } else {
        int j = blockIdx.x - kB;
        const float* x = tmem + (size_t)(kB + j) * kD;
        float* outp = g_negs + (size_t)(kB + j) * kD;
        float ss = 0.f;
        for (int i = t; i < kD; i += 256) { float v = x[i]; ss += v * v; }
        ss = warp_sum(ss);
        if ((t & 31) == 0) red[t >> 5] = ss;
        __syncthreads();
        float tot = red[0] + red[1] + red[2] + red[3] + red[4] + red[5] + red[6] + red[7];
        float inv = 1.0f / fmaxf(sqrtf(tot), kEps);
        for (int i = t; i < kD; i += 256) outp[i] = x[i] * inv;
    }
}

// ----- NT GEMM, pair-A / dup-B FFMA2: C = A(MxK) @ B(NxK)^T + bias ------------
// 64x64 tile, BK=16, 256 threads, 4x4 micro-tile (2 row-pairs x 4 cols).
__global__ void __launch_bounds__(256)
k_gemm_nt(const float* __restrict__ A, int lda, int sAz,
          const float* __restrict__ Bm, int ldb, int sBz,
          const float* __restrict__ bias, int sBiasz,
          float* __restrict__ C, int ldc, int sCz, int K) {
    A  += (size_t)blockIdx.z * sAz + (size_t)blockIdx.y * 64 * lda;
    Bm += (size_t)blockIdx.z * sBz + (size_t)blockIdx.x * 64 * ldb;
    C  += (size_t)blockIdx.z * sCz + (size_t)blockIdx.y * 64 * ldc + blockIdx.x * 64;
    int biasOff = blockIdx.z * sBiasz + blockIdx.x * 64;

    __shared__ __align__(16) float As [16][64];    // A plain: [k][row]
    __shared__ __align__(16) float Bsd[16][128];   // B dup:   [k][2*col]
    int tid = threadIdx.x;
    int tx = tid & 15, ty = tid >> 4;
    int lr = tid >> 2, lk = (tid & 3) << 2;

    const float* Aload = A + (size_t)lr * lda + lk;
    const float* Bload = Bm + (size_t)lr * ldb + lk;
    float4 a4 = *(const float4*)Aload;
    float4 b4 = *(const float4*)Bload;

    unsigned long long acc[2][4] = {};
    for (int k0 = 0; k0 < K; k0 += 16) {
        As[lk + 0][lr] = a4.x; As[lk + 1][lr] = a4.y;
        As[lk + 2][lr] = a4.z; As[lk + 3][lr] = a4.w;
        *(unsigned long long*)&Bsd[lk + 0][2 * lr] = dup2(b4.x);
        *(unsigned long long*)&Bsd[lk + 1][2 * lr] = dup2(b4.y);
        *(unsigned long long*)&Bsd[lk + 2][2 * lr] = dup2(b4.z);
        *(unsigned long long*)&Bsd[lk + 3][2 * lr] = dup2(b4.w);
        __syncthreads();
        if (k0 + 16 < K) {
            a4 = *(const float4*)(Aload + k0 + 16);
            b4 = *(const float4*)(Bload + k0 + 16);
        }
#pragma unroll
        for (int k = 0; k < 16; k++) {
            ulonglong2 ar = *(const ulonglong2*)&As[k][ty * 4];   // rows (4ty..4ty+3) as 2 pairs
            ulonglong2 b0 = *(const ulonglong2*)&Bsd[k][tx * 8];  // cols 4tx,4tx+1 dup'd
            ulonglong2 b1 = *(const ulonglong2*)&Bsd[k][tx * 8 + 4];
            fma2(acc[0][0], ar.x, b0.x); fma2(acc[0][1], ar.x, b0.y);
            fma2(acc[0][2], ar.x, b1.x); fma2(acc[0][3], ar.x, b1.y);
            fma2(acc[1][0], ar.y, b0.x); fma2(acc[1][1], ar.y, b0.y);
            fma2(acc[1][2], ar.y, b1.x); fma2(acc[1][3], ar.y, b1.y);
        }
        __syncthreads();
    }
    float4 bv = make_float4(0.f, 0.f, 0.f, 0.f);
    if (bias) {
        bv.x = bias[biasOff + tx * 4 + 0]; bv.y = bias[biasOff + tx * 4 + 1];
        bv.z = bias[biasOff + tx * 4 + 2]; bv.w = bias[biasOff + tx * 4 + 3];
    }
#pragma unroll
    for (int p = 0; p < 2; p++) {
        float2 c0 = unpack2(acc[p][0]);
        float2 c1 = unpack2(acc[p][1]);
        float2 c2 = unpack2(acc[p][2]);
        float2 c3 = unpack2(acc[p][3]);
        float4 vlo = make_float4(c0.x + bv.x, c1.x + bv.y, c2.x + bv.z, c3.x + bv.w);
        float4 vhi = make_float4(c0.y + bv.x, c1.y + bv.y, c2.y + bv.z, c3.y + bv.w);
        *(float4*)&C[(size_t)(ty * 4 + 2 * p + 0) * ldc + tx * 4] = vlo;
        *(float4*)&C[(size_t)(ty * 4 + 2 * p + 1) * ldc + tx * 4] = vhi;
    }
}

// ----- qt[b,h,d] = (1/8) * sum_dh q[b,h,dh] * Wk[h*64+dh, d]  (NN, K=64) ------
__global__ void __launch_bounds__(256)
k_qt_kernel(const float* __restrict__ wk) {
    int h = blockIdx.z, b0 = blockIdx.y * 64, d0 = blockIdx.x * 64;
    __shared__ __align__(16) float Qs [64][64];    // [dh][b], pre-scaled 1/8
    __shared__ __align__(16) float Wsd[64][128];   // [dh][2*d] dup'd
    int tid = threadIdx.x;

    {   // Q tile (rows=b, cols=dh) -> transposed, ×1/8
        int lr = tid >> 2, lk = (tid & 3) << 2;
        const float* qrow = g_q + (size_t)(b0 + lr) * kD + h * kDH;
#pragma unroll
        for (int c = 0; c < 4; c++) {
            float4 v = *(const float4*)(qrow + lk + c * 16);
            int cc = lk + c * 16;
            Qs[cc + 0][lr] = 0.125f * v.x; Qs[cc + 1][lr] = 0.125f * v.y;
            Qs[cc + 2][lr] = 0.125f * v.z; Qs[cc + 3][lr] = 0.125f * v.w;
        }
    }
    {   // W tile (rows=dh, cols=d) dup'd along cols
        int wr = tid >> 2, wc = (tid & 3) << 2;
        const float* wrow = wk + (size_t)(h * kDH + wr) * kD + d0;
#pragma unroll
        for (int c = 0; c < 4; c++) {
            float4 v = *(const float4*)(wrow + wc + c * 16);
            int cc = wc + c * 16;
            *(unsigned long long*)&Wsd[wr][2 * cc + 0] = dup2(v.x);
            *(unsigned long long*)&Wsd[wr][2 * cc + 2] = dup2(v.y);
            *(unsigned long long*)&Wsd[wr][2 * cc + 4] = dup2(v.z);
            *(unsigned long long*)&Wsd[wr][2 * cc + 6] = dup2(v.w);
        }
    }
    __syncthreads();

    int tx = tid & 15, ty = tid >> 4;
    unsigned long long acc[2][4] = {};
#pragma unroll 8
    for (int k = 0; k < 64; k++) {
        ulonglong2 ar = *(const ulonglong2*)&Qs[k][ty * 4];
        ulonglong2 b0 = *(const ulonglong2*)&Wsd[k][tx * 8];
        ulonglong2 b1 = *(const ulonglong2*)&Wsd[k][tx * 8 + 4];
        fma2(acc[0][0], ar.x, b0.x); fma2(acc[0][1], ar.x, b0.y);
        fma2(acc[0][2], ar.x, b1.x); fma2(acc[0][3], ar.x, b1.y);
        fma2(acc[1][0], ar.y, b0.x); fma2(acc[1][1], ar.y, b0.y);
        fma2(acc[1][2], ar.y, b1.x); fma2(acc[1][3], ar.y, b1.y);
    }
#pragma unroll
    for (int p = 0; p < 2; p++) {
        float2 c0 = unpack2(acc[p][0]);
        float2 c1 = unpack2(acc[p][1]);
        float2 c2 = unpack2(acc[p][2]);
        float2 c3 = unpack2(acc[p][3]);
        int rlo = b0 + ty * 4 + 2 * p;
        *(float4*)&g_qt[(size_t)(rlo + 0) * (kH * kD) + (size_t)h * kD + d0 + tx * 4]
            = make_float4(c0.x, c1.x, c2.x, c3.x);
        *(float4*)&g_qt[(size_t)(rlo + 1) * (kH * kD) + (size_t)h * kD + d0 + tx * 4]
            = make_float4(c0.y, c1.y, c2.y, c3.y);
    }
}

// ----- fused per-b: sims + sort/cluster + logits + softmax + tctx -------------
__global__ void __launch_bounds__(256)
k_attn(const float* __restrict__ text, float* __restrict__ out_cs) {
    __shared__ float sims[128];
    __shared__ __align__(16) float attn2[kM][kH];
    int b = blockIdx.x, t = threadIdx.x;
    int w = t >> 5, lane = t & 31;                  // 8 warps

    float qa[kH][16];
    {
        const float4* qt4 = (const float4*)(g_qt + (size_t)b * kH * kD);
#pragma unroll
        for (int h = 0; h < kH; h++)
#pragma unroll
            for (int j = 0; j < 4; j++) {
                float4 v = qt4[h * 128 + lane + 32 * j];
                qa[h][j * 4 + 0] = v.x; qa[h][j * 4 + 1] = v.y;
                qa[h][j * 4 + 2] = v.z; qa[h][j * 4 + 3] = v.w;
            }
    }
    float vnr[16];
    {
        const float4* vn4 = (const float4*)(g_vn + (size_t)b * kD);
#pragma unroll
        for (int j = 0; j < 4; j++) {
            float4 v = vn4[lane + 32 * j];
            vnr[j * 4 + 0] = v.x; vnr[j * 4 + 1] = v.y;
            vnr[j * 4 + 2] = v.z; vnr[j * 4 + 3] = v.w;
        }
    }

    const float4* trow = (const float4*)(text + (size_t)b * kM * kD);
    float4 pre[4];
    {
        const float4* r = trow + (size_t)w * 128;
#pragma unroll
        for (int j = 0; j < 4; j++) pre[j] = r[lane + 32 * j];
    }
    for (int m = w; m < kM; m += 8) {
        float tx[16];
#pragma unroll
        for (int j = 0; j < 4; j++) {
            tx[j * 4 + 0] = pre[j].x; tx[j * 4 + 1] = pre[j].y;
            tx[j * 4 + 2] = pre[j].z; tx[j * 4 + 3] = pre[j].w;
        }
        if (m + 8 < kM) {
            const float4* r = trow + (size_t)(m + 8) * 128;
#pragma unroll
            for (int j = 0; j < 4; j++) pre[j] = r[lane + 32 * j];
        }
        float dot = 0.f, ss = 0.f, a[kH] = {};
#pragma unroll
        for (int i = 0; i < 16; i++) {
            float tv = tx[i];
            dot += vnr[i] * tv; ss += tv * tv;
#pragma unroll
            for (int h = 0; h < kH; h++) a[h] += qa[h][i] * tv;
        }
        dot = warp_sum(dot); ss = warp_sum(ss);
#pragma unroll
        for (int h = 0; h < kH; h++) a[h] = warp_sum(a[h]);
        if (lane == 0) {
            sims[m] = dot / fmaxf(sqrtf(ss), kEps);
#pragma unroll
            for (int h = 0; h < kH; h++) attn2[m][h] = a[h];
        }
    }
    if (t >= kM && t < 128) sims[t] = -1e30f;
    __syncthreads();

    for (int k = 2; k <= 128; k <<= 1)
        for (int j = k >> 1; j > 0; j >>= 1) {
            if (t < 128) {
                int ixj = t ^ j;
                if (ixj > t) {
                    float a = sims[t], c = sims[ixj];
                    bool up = ((t & k) == 0);
                    if ((a > c) == up) { sims[t] = c; sims[ixj] = a; }
                }
            }
            __syncthreads();
        }

    if (t < kM) {
        float v = sims[127 - t];
        float mean = warp_sum(v) * (1.0f / 32.0f);
        float dv = v - mean;
        float var = warp_sum(dv * dv) * (1.0f / 31.0f);
        if (lane == 0) out_cs[b * kNC + (t >> 5)] = mean / (sqrtf(var) + 1e-6f);
    }

    {
        int h = w;
        float v0 = attn2[lane][h], v1 = attn2[lane + 32][h], v2 = attn2[lane + 64][h];
        float mx = warp_max(fmaxf(v0, fmaxf(v1, v2)));
        v0 = expf(v0 - mx); v1 = expf(v1 - mx); v2 = expf(v2 - mx);
        float inv = 1.0f / warp_sum(v0 + v1 + v2);
        attn2[lane][h] = v0 * inv; attn2[lane + 32][h] = v1 * inv; attn2[lane + 64][h] = v2 * inv;
    }
    __syncthreads();

    float2 acc[kH] = {};
    const float2* rb = (const float2*)(text + (size_t)b * kM * kD);
#pragma unroll 8
    for (int m = 0; m < kM; m++) {
        float2 tv = rb[(size_t)m * 256 + t];
        float4 a0 = *(const float4*)&attn2[m][0];
        float4 a1 = *(const float4*)&attn2[m][4];
        acc[0].x += a0.x * tv.x; acc[0].y += a0.x * tv.y;
        acc[1].x += a0.y * tv.x; acc[1].y += a0.y * tv.y;
        acc[2].x += a0.z * tv.x; acc[2].y += a0.z * tv.y;
        acc[3].x += a0.w * tv.x; acc[3].y += a0.w * tv.y;
        acc[4].x += a1.x * tv.x; acc[4].y += a1.x * tv.y;
        acc[5].x += a1.y * tv.x; acc[5].y += a1.y * tv.y;
        acc[6].x += a1.z * tv.x; acc[6].y += a1.z * tv.y;
        acc[7].x += a1.w * tv.x; acc[7].y += a1.w * tv.y;
    }
    float* tb = g_tctx + (size_t)b * kH * kD;
#pragma unroll
    for (int h = 0; h < kH; h++) ((float2*)(tb + h * kD))[t] = acc[h];
}

// ----- combine split-K partials + opb, copy to d_out, normalize, pos_sim ------
__global__ void k_cn_pos(float* __restrict__ out_corr, const float* __restrict__ opb) {
    int b = blockIdx.x, t = threadIdx.x;  // 256
    const float* x0 = g_corr + (size_t)b * kD;
    const float* x1 = g_corr + (size_t)kB * kD + (size_t)b * kD;
    const float* vnb = g_vn + (size_t)b * kD;
    float vals[2];
    float ss = 0.f, dt = 0.f;
#pragma unroll
    for (int j = 0; j < 2; j++) {
        int i = t + j * 256;
        float v = x0[i] + x1[i] + opb[i];
        vals[j] = v;
        out_corr[(size_t)b * kD + i] = v;
        ss += v * v; dt += vnb[i] * v;
    }
    __shared__ float rs[8], rd[8];
    ss = warp_sum(ss); dt = warp_sum(dt);
    if ((t & 31) == 0) { rs[t >> 5] = ss; rd[t >> 5] = dt; }
    __syncthreads();
    float s2 = rs[0] + rs[1] + rs[2] + rs[3] + rs[4] + rs[5] + rs[6] + rs[7];
    float d2 = rd[0] + rd[1] + rd[2] + rd[3] + rd[4] + rd[5] + rd[6] + rd[7];
    float inv = 1.0f / fmaxf(sqrtf(s2), kEps);
    if (t == 0) g_pos[b] = d2 * inv;
#pragma unroll
    for (int j = 0; j < 2; j++)
        g_negs[(size_t)b * kD + t + j * 256] = vals[j] * inv;
}

// ----- warp-per-b top-5 (cn sims count twice) + loss term ---------------------
__device__ __forceinline__ void ins5(float (&t5)[5], float v) {
    if (v > t5[4]) {
        t5[4] = v;
        if (t5[4] > t5[3]) { float tm = t5[3]; t5[3] = t5[4]; t5[4] = tm; }
        if (t5[3] > t5[2]) { float tm = t5[2]; t5[2] = t5[3]; t5[3] = tm; }
        if (t5[2] > t5[1]) { float tm = t5[1]; t5[1] = t5[2]; t5[2] = tm; }
        if (t5[1] > t5[0]) { float tm = t5[0]; t5[0] = t5[1]; t5[1] = tm; }
    }
}
__global__ void __launch_bounds__(512)
k_loss(const float* __restrict__ tpl, const float* __restrict__ tnl) {
    int b = blockIdx.x * 16 + (threadIdx.x >> 5);
    int lane = threadIdx.x & 31;
    const float* ns = g_nsims + (size_t)b * kNegC;
    float t5[5] = {-1e30f, -1e30f, -1e30f, -1e30f, -1e30f};
    for (int i = lane; i < 512; i += 32) {      // cn sims: multiplicity 2
        float v = ns[i];
        ins5(t5, v); ins5(t5, v);
    }
    for (int i = 512 + lane; i < 1024; i += 32) // mem sims
        ins5(t5, ns[i]);

    float tau_n = expf(tnl[0]);
    int ptr = 0;
    float neg = 0.f;
#pragma unroll
    for (int r = 0; r < 5; r++) {
        float mine = (ptr == 0) ? t5[0] : (ptr == 1) ? t5[1] : (ptr == 2) ? t5[2]
                   : (ptr == 3) ? t5[3] : (ptr == 4) ? t5[4] : -1e30f;
        float mx = warp_max(mine);
        unsigned bal = __ballot_sync(0xffffffffu, mine == mx);
        if (lane == (__ffs(bal) - 1)) ptr++;
        neg += expf(mx / tau_n);
    }
    if (lane == 0) {
        float tau_p = expf(tpl[0]);
        float pos = expf(g_pos[b] / tau_p);
        g_lossb[b] = logf(pos / (pos + neg + 1e-8f));
    }
}

__global__ void k_final(float* __restrict__ out) {
    int t = threadIdx.x;  // 512
    float v = g_lossb[t];
    __shared__ float red[16];
    v = warp_sum(v);
    if ((t & 31) == 0) red[t >> 5] = v;
    __syncthreads();
    if (t < 32) {
        float s = (t < 16) ? red[t] : 0.f;
        s = warp_sum(s);
        if (t == 0) out[0] = -s / (float)kB;
    }
}

// ---------------------------------------------------------------------------
extern "C" void kernel_launch(void* const* d_in, const int* in_sizes, int n_in,
                              void* d_out, int out_size) {
    const float* vis  = (const float*)d_in[0];
    const float* text = (const float*)d_in[1];
    const float* ipw  = (const float*)d_in[2];
    const float* ipb  = (const float*)d_in[3];
    const float* opw  = (const float*)d_in[4];
    const float* opb  = (const float*)d_in[5];
    const float* tmem = (const float*)d_in[6];
    const float* tpl  = (const float*)d_in[7];
    const float* tnl  = (const float*)d_in[8];

    float* out      = (float*)d_out;
    float* out_corr = out + 1;
    float* out_cs   = out + 1 + kB * kD;

    float *p_q, *p_vn, *p_tctx, *p_ctx, *p_corr, *p_negs, *p_nsims;
    cudaGetSymbolAddress((void**)&p_q,     g_q);
    cudaGetSymbolAddress((void**)&p_vn,    g_vn);
    cudaGetSymbolAddress((void**)&p_tctx,  g_tctx);
    cudaGetSymbolAddress((void**)&p_ctx,   g_ctx);
    cudaGetSymbolAddress((void**)&p_corr,  g_corr);
    cudaGetSymbolAddress((void**)&p_negs,  g_negs);
    cudaGetSymbolAddress((void**)&p_nsims, g_nsims);

    // 1. normalize vis rows + memory negatives (one launch)
    k_pre<<<2 * kB, 256>>>(vis, tmem);
    // 2. q = vis @ Wq^T + bq
    k_gemm_nt<<<dim3(kD / 64, kB / 64, 1), 256>>>(vis, kD, 0, ipw, kD, 0, ipb, 0,
                                                  p_q, kD, 0, kD);
    // 3. qt = (1/8) q_h @ Wk_h   (per head)
    k_qt_kernel<<<dim3(kD / 64, kB / 64, kH), 256>>>(ipw + (size_t)kD * kD);
    // 4. fused attention: sims + clustering + logits + softmax + tctx
    k_attn<<<kB, 256>>>(text, out_cs);
    // 5. ctx_h = tctx_h @ Wv_h^T + bv_h   (block-diagonal, grid.z = head)
    k_gemm_nt<<<dim3(1, kB / 64, kH), 256>>>(p_tctx, kH * kD, kD,
                                             ipw + 2 * (size_t)kD * kD, kD, kDH * kD,
                                             ipb + 2 * kD, kDH,
                                             p_ctx, kD, kDH, kD);
    // 6. corrected partials = ctx @ Wo^T  (split-K x2, z = K-half)
    k_gemm_nt<<<dim3(kD / 64, kB / 64, 2), 256>>>(p_ctx, kD, 256, opw, kD, 256,
                                                  nullptr, 0,
                                                  p_corr, kD, kB * kD, 256);
    // 7. combine partials + opb -> d_out, normalize into g_negs[0:512], pos_sim
    k_cn_pos<<<kB, 256>>>(out_corr, opb);
    // 8. neg_sims = vn @ negs^T   (512 x 1024 x 512)
    k_gemm_nt<<<dim3(kNegC / 64, kB / 64, 1), 256>>>(p_vn, kD, 0, p_negs, kD, 0,
                                                     nullptr, 0, p_nsims, kNegC, 0, kD);
    // 9. top-5 (with multiplicity) + per-row loss
    k_loss<<<kB / 16, 512>>>(tpl, tnl);
    // 10. mean reduce -> loss scalar
    k_final<<<1, 512>>>(out);
}

// round 6
// speedup vs baseline: 1.5074x; 1.5074x over previous
#include <cuda_runtime.h>

// ---------------------------------------------------------------------------
// DiscriminativeClueCorrection — fp32, FFMA2 GEMMs (dup-A layout, R4-proven),
// d-chunked low-register fused attention.
// Output layout (float32): [loss(1)] [corrected(512*512)] [cluster_scores(512*3)]
// ---------------------------------------------------------------------------

constexpr int kB    = 512;
constexpr int kM    = 96;
constexpr int kD    = 512;
constexpr int kH    = 8;
constexpr int kDH   = 64;
constexpr int kNC   = 3;
constexpr int kNegC = 1024;
constexpr float kEps = 1e-8f;

// ----- device scratch --------------------------------------------------------
__device__ float g_vn   [kB * kD];
__device__ float g_q    [kB * kD];
__device__ float g_qt   [kB * kH * kD];     // per-b transformed key weights (×1/8)
__device__ float g_tctx [kB * kH * kD];
__device__ float g_ctx  [kB * kD];
__device__ float g_corr [2 * kB * kD];      // split-K partials
__device__ float g_pos  [kB];
__device__ float g_negs [kNegC * kD];
__device__ float g_nsims[kB * kNegC];
__device__ float g_lossb[kB];

__device__ __forceinline__ float warp_sum(float v) {
#pragma unroll
    for (int o = 16; o > 0; o >>= 1) v += __shfl_xor_sync(0xffffffffu, v, o);
    return v;
}
__device__ __forceinline__ float warp_max(float v) {
#pragma unroll
    for (int o = 16; o > 0; o >>= 1) v = fmaxf(v, __shfl_xor_sync(0xffffffffu, v, o));
    return v;
}

// ----- f32x2 packed helpers ---------------------------------------------------
__device__ __forceinline__ unsigned long long dup2(float v) {
    unsigned long long r;
    asm("mov.b64 %0, {%1,%1};" : "=l"(r) : "f"(v));
    return r;
}
__device__ __forceinline__ void fma2(unsigned long long& acc, unsigned long long a,
                                     unsigned long long b) {
    asm("fma.rn.f32x2 %0, %1, %2, %0;" : "+l"(acc) : "l"(a), "l"(b));
}
__device__ __forceinline__ float2 unpack2(unsigned long long v) {
    float2 f;
    asm("mov.b64 {%0,%1}, %2;" : "=f"(f.x), "=f"(f.y) : "l"(v));
    return f;
}

// ----- merged: normalize vis rows (blocks 0..511) + memory negs (512..1023) ---
__global__ void k_pre(const float* __restrict__ vis, const float* __restrict__ tmem) {
    int t = threadIdx.x;                     // 256 threads
    __shared__ float red[8];
    const float* x;
    float* outp;
    if (blockIdx.x < kB) {
        x = vis + (size_t)blockIdx.x * kD;
        outp = g_vn + (size_t)blockIdx.x * kD;
    } else {
        x = tmem + (size_t)blockIdx.x * kD;            // rows 512..1023
        outp = g_negs + (size_t)blockIdx.x * kD;
    }
    float ss = 0.f;
    for (int i = t; i < kD; i += 256) { float v = x[i]; ss += v * v; }
    ss = warp_sum(ss);
    if ((t & 31) == 0) red[t >> 5] = ss;
    __syncthreads();
    float tot = red[0] + red[1] + red[2] + red[3] + red[4] + red[5] + red[6] + red[7];
    float inv = 1.0f / fmaxf(sqrtf(tot), kEps);
    for (int i = t; i < kD; i += 256) outp[i] = x[i] * inv;
}

// ----- NT GEMM with FFMA2 (R4 dup-A layout): C = A@B^T + bias, 64x64, BK=16 ---
__global__ void __launch_bounds__(256)
k_gemm_nt(const float* __restrict__ A, int lda, int sAz,
          const float* __restrict__ Bm, int ldb, int sBz,
          const float* __restrict__ bias, int sBiasz,
          float* __restrict__ C, int ldc, int sCz, int K) {
    A  += (size_t)blockIdx.z * sAz + (size_t)blockIdx.y * 64 * lda;
    Bm += (size_t)blockIdx.z * sBz + (size_t)blockIdx.x * 64 * ldb;
    C  += (size_t)blockIdx.z * sCz + (size_t)blockIdx.y * 64 * ldc + blockIdx.x * 64;
    int biasOff = blockIdx.z * sBiasz + blockIdx.x * 64;

    __shared__ __align__(16) float As2[16][128];   // A duplicated: [k][2r],[k][2r+1]
    __shared__ __align__(16) float Bs[16][64];
    int tid = threadIdx.x;
    int tx = tid & 15, ty = tid >> 4;
    int lr = tid >> 2, lk = (tid & 3) << 2;

    const float* Aload = A + (size_t)lr * lda + lk;
    const float* Bload = Bm + (size_t)lr * ldb + lk;
    float4 a4 = *(const float4*)Aload;
    float4 b4 = *(const float4*)Bload;

    unsigned long long acc[4][2] = {};
    for (int k0 = 0; k0 < K; k0 += 16) {
        *(unsigned long long*)&As2[lk + 0][2 * lr] = dup2(a4.x);
        *(unsigned long long*)&As2[lk + 1][2 * lr] = dup2(a4.y);
        *(unsigned long long*)&As2[lk + 2][2 * lr] = dup2(a4.z);
        *(unsigned long long*)&As2[lk + 3][2 * lr] = dup2(a4.w);
        Bs[lk + 0][lr] = b4.x; Bs[lk + 1][lr] = b4.y;
        Bs[lk + 2][lr] = b4.z; Bs[lk + 3][lr] = b4.w;
        __syncthreads();
        if (k0 + 16 < K) {
            a4 = *(const float4*)(Aload + k0 + 16);
            b4 = *(const float4*)(Bload + k0 + 16);
        }
#pragma unroll
        for (int k = 0; k < 16; k++) {
            ulonglong2 ap0 = *(const ulonglong2*)&As2[k][ty * 8];
            ulonglong2 ap1 = *(const ulonglong2*)&As2[k][ty * 8 + 4];
            ulonglong2 bp  = *(const ulonglong2*)&Bs[k][tx * 4];
            fma2(acc[0][0], ap0.x, bp.x); fma2(acc[0][1], ap0.x, bp.y);
            fma2(acc[1][0], ap0.y, bp.x); fma2(acc[1][1], ap0.y, bp.y);
            fma2(acc[2][0], ap1.x, bp.x); fma2(acc[2][1], ap1.x, bp.y);
            fma2(acc[3][0], ap1.y, bp.x); fma2(acc[3][1], ap1.y, bp.y);
        }
        __syncthreads();
    }
#pragma unroll
    for (int i = 0; i < 4; i++) {
        int row = ty * 4 + i;
        int col = tx * 4;
        float2 c0 = unpack2(acc[i][0]);
        float2 c1 = unpack2(acc[i][1]);
        float4 v = make_float4(c0.x, c0.y, c1.x, c1.y);
        if (bias) {
            v.x += bias[biasOff + col + 0]; v.y += bias[biasOff + col + 1];
            v.z += bias[biasOff + col + 2]; v.w += bias[biasOff + col + 3];
        }
        *(float4*)&C[(size_t)row * ldc + col] = v;
    }
}

// ----- qt[b,h,d] = (1/8) * sum_dh q[b,h,dh] * Wk[h*64+dh, d]  (R4 layout) -----
__global__ void __launch_bounds__(256)
k_qt_kernel(const float* __restrict__ wk) {
    int h = blockIdx.z, b0 = blockIdx.y * 64, d0 = blockIdx.x * 64;
    __shared__ __align__(16) float Qs2[64][128];   // [dh][2b] duplicated
    __shared__ __align__(16) float Ws[64][64];     // [dh][d], pre-scaled by 1/8
    int tid = threadIdx.x;

    {
        int lr = tid >> 2, lk = (tid & 3) << 2;
        const float* qrow = g_q + (size_t)(b0 + lr) * kD + h * kDH;
#pragma unroll
        for (int c = 0; c < 4; c++) {
            float4 v = *(const float4*)(qrow + lk + c * 16);
            int cc = lk + c * 16;
            *(unsigned long long*)&Qs2[cc + 0][2 * lr] = dup2(v.x);
            *(unsigned long long*)&Qs2[cc + 1][2 * lr] = dup2(v.y);
            *(unsigned long long*)&Qs2[cc + 2][2 * lr] = dup2(v.z);
            *(unsigned long long*)&Qs2[cc + 3][2 * lr] = dup2(v.w);
        }
    }
    {
        int wr = tid >> 2, wc = (tid & 3) << 2;
        const float* wrow = wk + (size_t)(h * kDH + wr) * kD + d0;
#pragma unroll
        for (int c = 0; c < 4; c++) {
            float4 v = *(const float4*)(wrow + wc + c * 16);
            v.x *= 0.125f; v.y *= 0.125f; v.z *= 0.125f; v.w *= 0.125f;
            *(float4*)&Ws[wr][wc + c * 16] = v;
        }
    }
    __syncthreads();

    int tx = tid & 15, ty = tid >> 4;
    unsigned long long acc[4][2] = {};
#pragma unroll 8
    for (int k = 0; k < 64; k++) {
        ulonglong2 ap0 = *(const ulonglong2*)&Qs2[k][ty * 8];
        ulonglong2 ap1 = *(const ulonglong2*)&Qs2[k][ty * 8 + 4];
        ulonglong2 bp  = *(const ulonglong2*)&Ws[k][tx * 4];
        fma2(acc[0][0], ap0.x, bp.x); fma2(acc[0][1], ap0.x, bp.y);
        fma2(acc[1][0], ap0.y, bp.x); fma2(acc[1][1], ap0.y, bp.y);
        fma2(acc[2][0], ap1.x, bp.x); fma2(acc[2][1], ap1.x, bp.y);
        fma2(acc[3][0], ap1.y, bp.x); fma2(acc[3][1], ap1.y, bp.y);
    }
#pragma unroll
    for (int i = 0; i < 4; i++) {
        float2 c0 = unpack2(acc[i][0]);
        float2 c1 = unpack2(acc[i][1]);
        float4 v = make_float4(c0.x, c0.y, c1.x, c1.y);
        *(float4*)&g_qt[(size_t)(b0 + ty * 4 + i) * (kH * kD) + (size_t)h * kD + d0 + tx * 4] = v;
    }
}

// ----- fused per-b: sims + sort/cluster + logits + softmax + tctx -------------
// 256 threads, d-chunked pass 1 (2 halves of d) -> qa is [8][8] (64 regs),
// partial logits/sims accumulated in smem. Forced 2 blocks/SM.
__global__ void __launch_bounds__(256, 2)
k_attn(const float* __restrict__ text, float* __restrict__ out_cs) {
    __shared__ float sdot[kM], sss[kM];
    __shared__ float sims[128];
    __shared__ __align__(16) float attn2[kM][kH];
    int b = blockIdx.x, t = threadIdx.x;
    int w = t >> 5, lane = t & 31;                  // 8 warps

    const float4* qt4  = (const float4*)(g_qt + (size_t)b * kH * kD);
    const float4* vn4  = (const float4*)(g_vn + (size_t)b * kD);
    const float4* trow = (const float4*)(text + (size_t)b * kM * kD);

    // ---- pass 1, two d-halves; warp handles m = w, w+8, ... ------------------
#pragma unroll 1
    for (int half = 0; half < 2; half++) {
        // qa[h][0..7]: head h, d-elements (half*256 + 4*(lane+32j) .. +3)
        float qa[kH][8];
#pragma unroll
        for (int h = 0; h < kH; h++)
#pragma unroll
            for (int j = 0; j < 2; j++) {
                float4 v = qt4[h * 128 + half * 64 + lane + 32 * j];
                qa[h][j * 4 + 0] = v.x; qa[h][j * 4 + 1] = v.y;
                qa[h][j * 4 + 2] = v.z; qa[h][j * 4 + 3] = v.w;
            }
        float vnr[8];
#pragma unroll
        for (int j = 0; j < 2; j++) {
            float4 v = vn4[half * 64 + lane + 32 * j];
            vnr[j * 4 + 0] = v.x; vnr[j * 4 + 1] = v.y;
            vnr[j * 4 + 2] = v.z; vnr[j * 4 + 3] = v.w;
        }

        float4 pre[2];
        {
            const float4* r = trow + (size_t)w * 128 + half * 64;
            pre[0] = r[lane]; pre[1] = r[lane + 32];
        }
        for (int m = w; m < kM; m += 8) {
            float tx[8];
            tx[0] = pre[0].x; tx[1] = pre[0].y; tx[2] = pre[0].z; tx[3] = pre[0].w;
            tx[4] = pre[1].x; tx[5] = pre[1].y; tx[6] = pre[1].z; tx[7] = pre[1].w;
            if (m + 8 < kM) {
                const float4* r = trow + (size_t)(m + 8) * 128 + half * 64;
                pre[0] = r[lane]; pre[1] = r[lane + 32];
            }
            float dot = 0.f, ss = 0.f, a[kH] = {};
#pragma unroll
            for (int i = 0; i < 8; i++) {
                float tv = tx[i];
                dot += vnr[i] * tv; ss += tv * tv;
#pragma unroll
                for (int h = 0; h < kH; h++) a[h] += qa[h][i] * tv;
            }
            dot = warp_sum(dot); ss = warp_sum(ss);
#pragma unroll
            for (int h = 0; h < kH; h++) a[h] = warp_sum(a[h]);
            if (lane == 0) {
                if (half == 0) {
                    sdot[m] = dot; sss[m] = ss;
#pragma unroll
                    for (int h = 0; h < kH; h++) attn2[m][h] = a[h];
                } else {
                    sdot[m] += dot; sss[m] += ss;
#pragma unroll
                    for (int h = 0; h < kH; h++) attn2[m][h] += a[h];
                }
            }
        }
    }
    __syncthreads();

    // finalize sims
    if (t < kM) sims[t] = sdot[t] / fmaxf(sqrtf(sss[t]), kEps);
    else if (t < 128) sims[t] = -1e30f;
    __syncthreads();

    // ---- bitonic ascending sort of sims[128] ---------------------------------
    for (int k = 2; k <= 128; k <<= 1)
        for (int j = k >> 1; j > 0; j >>= 1) {
            if (t < 128) {
                int ixj = t ^ j;
                if (ixj > t) {
                    float a = sims[t], c = sims[ixj];
                    bool up = ((t & k) == 0);
                    if ((a > c) == up) { sims[t] = c; sims[ixj] = a; }
                }
            }
            __syncthreads();
        }

    // ---- cluster stats on descending groups of 32 (warps 0..2) ---------------
    if (t < kM) {
        float v = sims[127 - t];
        float mean = warp_sum(v) * (1.0f / 32.0f);
        float dv = v - mean;
        float var = warp_sum(dv * dv) * (1.0f / 31.0f);
        if (lane == 0) out_cs[b * kNC + (t >> 5)] = mean / (sqrtf(var) + 1e-6f);
    }

    // ---- softmax over m per head (warp w = head) ------------------------------
    {
        int h = w;
        float v0 = attn2[lane][h], v1 = attn2[lane + 32][h], v2 = attn2[lane + 64][h];
        float mx = warp_max(fmaxf(v0, fmaxf(v1, v2)));
        v0 = expf(v0 - mx); v1 = expf(v1 - mx); v2 = expf(v2 - mx);
        float inv = 1.0f / warp_sum(v0 + v1 + v2);
        attn2[lane][h] = v0 * inv; attn2[lane + 32][h] = v1 * inv; attn2[lane + 64][h] = v2 * inv;
    }
    __syncthreads();

    // ---- pass 2: tctx[h][d] = sum_m attn[m][h]*text[m][d]; thread owns float2 -
    float2 acc[kH] = {};
    const float2* rb = (const float2*)(text + (size_t)b * kM * kD);
#pragma unroll 8
    for (int m = 0; m < kM; m++) {
        float2 tv = rb[(size_t)m * 256 + t];
        float4 a0 = *(const float4*)&attn2[m][0];
        float4 a1 = *(const float4*)&attn2[m][4];
        acc[0].x += a0.x * tv.x; acc[0].y += a0.x * tv.y;
        acc[1].x += a0.y * tv.x; acc[1].y += a0.y * tv.y;
        acc[2].x += a0.z * tv.x; acc[2].y += a0.z * tv.y;
        acc[3].x += a0.w * tv.x; acc[3].y += a0.w * tv.y;
        acc[4].x += a1.x * tv.x; acc[4].y += a1.x * tv.y;
        acc[5].x += a1.y * tv.x; acc[5].y += a1.y * tv.y;
        acc[6].x += a1.z * tv.x; acc[6].y += a1.z * tv.y;
        acc[7].x += a1.w * tv.x; acc[7].y += a1.w * tv.y;
    }
    float* tb = g_tctx + (size_t)b * kH * kD;
#pragma unroll
    for (int h = 0; h < kH; h++) ((float2*)(tb + h * kD))[t] = acc[h];
}

// ----- combine split-K partials + opb, copy to d_out, normalize, pos_sim ------
__global__ void k_cn_pos(float* __restrict__ out_corr, const float* __restrict__ opb) {
    int b = blockIdx.x, t = threadIdx.x;  // 256
    const float* x0 = g_corr + (size_t)b * kD;
    const float* x1 = g_corr + (size_t)kB * kD + (size_t)b * kD;
    const float* vnb = g_vn + (size_t)b * kD;
    float vals[2];
    float ss = 0.f, dt = 0.f;
#pragma unroll
    for (int j = 0; j < 2; j++) {
        int i = t + j * 256;
        float v = x0[i] + x1[i] + opb[i];
        vals[j] = v;
        out_corr[(size_t)b * kD + i] = v;
        ss += v * v; dt += vnb[i] * v;
    }
    __shared__ float rs[8], rd[8];
    ss = warp_sum(ss); dt = warp_sum(dt);
    if ((t & 31) == 0) { rs[t >> 5] = ss; rd[t >> 5] = dt; }
    __syncthreads();
    float s2 = rs[0] + rs[1] + rs[2] + rs[3] + rs[4] + rs[5] + rs[6] + rs[7];
    float d2 = rd[0] + rd[1] + rd[2] + rd[3] + rd[4] + rd[5] + rd[6] + rd[7];
    float inv = 1.0f / fmaxf(sqrtf(s2), kEps);
    if (t == 0) g_pos[b] = d2 * inv;
#pragma unroll
    for (int j = 0; j < 2; j++)
        g_negs[(size_t)b * kD + t + j * 256] = vals[j] * inv;
}

// ----- warp-per-b top-5 (cn sims count twice) + loss term ---------------------
__device__ __forceinline__ void ins5(float (&t5)[5], float v) {
    if (v > t5[4]) {
        t5[4] = v;
        if (t5[4] > t5[3]) { float tm = t5[3]; t5[3] = t5[4]; t5[4] = tm; }
        if (t5[3] > t5[2]) { float tm = t5[2]; t5[2] = t5[3]; t5[3] = tm; }
        if (t5[2] > t5[1]) { float tm = t5[1]; t5[1] = t5[2]; t5[2] = tm; }
        if (t5[1] > t5[0]) { float tm = t5[0]; t5[0] = t5[1]; t5[1] = tm; }
    }
}
__global__ void __launch_bounds__(512)
k_loss(const float* __restrict__ tpl, const float* __restrict__ tnl) {
    int b = blockIdx.x * 16 + (threadIdx.x >> 5);
    int lane = threadIdx.x & 31;
    const float* ns = g_nsims + (size_t)b * kNegC;
    float t5[5] = {-1e30f, -1e30f, -1e30f, -1e30f, -1e30f};
    for (int i = lane; i < 512; i += 32) {      // cn sims: multiplicity 2
        float v = ns[i];
        ins5(t5, v); ins5(t5, v);
    }
    for (int i = 512 + lane; i < 1024; i += 32) // mem sims
        ins5(t5, ns[i]);

    float tau_n = expf(tnl[0]);
    int ptr = 0;
    float neg = 0.f;
#pragma unroll
    for (int r = 0; r < 5; r++) {
        float mine = (ptr == 0) ? t5[0] : (ptr == 1) ? t5[1] : (ptr == 2) ? t5[2]
                   : (ptr == 3) ? t5[3] : (ptr == 4) ? t5[4] : -1e30f;
        float mx = warp_max(mine);
        unsigned bal = __ballot_sync(0xffffffffu, mine == mx);
        if (lane == (__ffs(bal) - 1)) ptr++;
        neg += expf(mx / tau_n);
    }
    if (lane == 0) {
        float tau_p = expf(tpl[0]);
        float pos = expf(g_pos[b] / tau_p);
        g_lossb[b] = logf(pos / (pos + neg + 1e-8f));
    }
}

__global__ void k_final(float* __restrict__ out) {
    int t = threadIdx.x;  // 512
    float v = g_lossb[t];
    __shared__ float red[16];
    v = warp_sum(v);
    if ((t & 31) == 0) red[t >> 5] = v;
    __syncthreads();
    if (t < 32) {
        float s = (t < 16) ? red[t] : 0.f;
        s = warp_sum(s);
        if (t == 0) out[0] = -s / (float)kB;
    }
}

// ---------------------------------------------------------------------------
extern "C" void kernel_launch(void* const* d_in, const int* in_sizes, int n_in,
                              void* d_out, int out_size) {
    const float* vis  = (const float*)d_in[0];
    const float* text = (const float*)d_in[1];
    const float* ipw  = (const float*)d_in[2];
    const float* ipb  = (const float*)d_in[3];
    const float* opw  = (const float*)d_in[4];
    const float* opb  = (const float*)d_in[5];
    const float* tmem = (const float*)d_in[6];
    const float* tpl  = (const float*)d_in[7];
    const float* tnl  = (const float*)d_in[8];

    float* out      = (float*)d_out;
    float* out_corr = out + 1;
    float* out_cs   = out + 1 + kB * kD;

    float *p_q, *p_vn, *p_tctx, *p_ctx, *p_corr, *p_negs, *p_nsims;
    cudaGetSymbolAddress((void**)&p_q,     g_q);
    cudaGetSymbolAddress((void**)&p_vn,    g_vn);
    cudaGetSymbolAddress((void**)&p_tctx,  g_tctx);
    cudaGetSymbolAddress((void**)&p_ctx,   g_ctx);
    cudaGetSymbolAddress((void**)&p_corr,  g_corr);
    cudaGetSymbolAddress((void**)&p_negs,  g_negs);
    cudaGetSymbolAddress((void**)&p_nsims, g_nsims);

    // 1. normalize vis rows + memory negatives (one launch)
    k_pre<<<2 * kB, 256>>>(vis, tmem);
    // 2. q = vis @ Wq^T + bq
    k_gemm_nt<<<dim3(kD / 64, kB / 64, 1), 256>>>(vis, kD, 0, ipw, kD, 0, ipb, 0,
                                                  p_q, kD, 0, kD);
    // 3. qt = (1/8) q_h @ Wk_h   (per head)
    k_qt_kernel<<<dim3(kD / 64, kB / 64, kH), 256>>>(ipw + (size_t)kD * kD);
    // 4. fused attention
    k_attn<<<kB, 256>>>(text, out_cs);
    // 5. ctx_h = tctx_h @ Wv_h^T + bv_h
    k_gemm_nt<<<dim3(1, kB / 64, kH), 256>>>(p_tctx, kH * kD, kD,
                                             ipw + 2 * (size_t)kD * kD, kD, kDH * kD,
                                             ipb + 2 * kD, kDH,
                                             p_ctx, kD, kDH, kD);
    // 6. corrected partials = ctx @ Wo^T  (split-K x2)
    k_gemm_nt<<<dim3(kD / 64, kB / 64, 2), 256>>>(p_ctx, kD, 256, opw, kD, 256,
                                                  nullptr, 0,
                                                  p_corr, kD, kB * kD, 256);
    // 7. combine + opb -> d_out, normalize into g_negs[0:512], pos_sim
    k_cn_pos<<<kB, 256>>>(out_corr, opb);
    // 8. neg_sims = vn @ negs^T
    k_gemm_nt<<<dim3(kNegC / 64, kB / 64, 1), 256>>>(p_vn, kD, 0, p_negs, kD, 0,
                                                     nullptr, 0, p_nsims, kNegC, 0, kD);
    // 9. top-5 (with multiplicity) + per-row loss
    k_loss<<<kB / 16, 512>>>(tpl, tnl);
    // 10. mean reduce -> loss scalar
    k_final<<<1, 512>>>(out);
}